// round 10
// baseline (speedup 1.0000x reference)
#include <cuda_runtime.h>
#include <cuda_bf16.h>
#include <cstdint>

#define NUM_B 32
#define NUM_C 128
#define NSEG (NUM_B * NUM_C)

#define THREADS 64
#define GRID_BLOCKS 456            // 3 CTAs/SM on 152 SMs

// Per-thread u32 bins: bits[0:24) = sum * 2^14, bits[24:32) = count.
#define P_CNT_SHIFT 24
#define P_SUM_MASK ((1u << P_CNT_SHIFT) - 1u)
#define P_SCALE 16384.0f
// Global u64 bins: bits[0:40) = sum * 2^14, bits[40:64) = count.
#define G_CNT_SHIFT 40
#define G_SUM_MASK ((1ULL << G_CNT_SHIFT) - 1ULL)
#define INV_SCALE (1.0f / 16384.0f)

// Stage geometry: 128 float4 (512 elements) per array per stage; 4-deep ring.
#define STAGE4 128
#define NBUF 4
#define ARR_BYTES (STAGE4 * 16)                    // 2048
#define BUF_STRIDE (4 * ARR_BYTES)                 // 8192
#define OFF_STAGE (THREADS * NUM_C * 4)            // 32768 (bins first)
#define OFF_MBAR (OFF_STAGE + NBUF * BUF_STRIDE)   // 65536
#define SMEM_BYTES (OFF_MBAR + 128)                // 65664 -> 3 CTAs/SM

struct alignas(128) PadBin {
    unsigned long long v;
    unsigned long long pad[15];
};
__device__ PadBin g_bins[NSEG];   // zero-init; last block re-zeros each run
__device__ unsigned int g_done;

// ---------------- PTX helpers ----------------
__device__ __forceinline__ uint32_t smem_u32(const void* p) {
    uint32_t a;
    asm("{ .reg .u64 t; cvta.to.shared.u64 t, %1; cvt.u32.u64 %0, t; }"
        : "=r"(a) : "l"(p));
    return a;
}
__device__ __forceinline__ void mbar_init(uint32_t a, uint32_t cnt) {
    asm volatile("mbarrier.init.shared.b64 [%0], %1;" :: "r"(a), "r"(cnt) : "memory");
}
__device__ __forceinline__ void mbar_expect_tx(uint32_t a, uint32_t tx) {
    asm volatile("mbarrier.arrive.expect_tx.shared.b64 _, [%0], %1;"
                 :: "r"(a), "r"(tx) : "memory");
}
__device__ __forceinline__ void bulk_g2s(uint32_t dst, const void* src,
                                         uint32_t bytes, uint32_t mbar) {
    asm volatile("cp.async.bulk.shared::cta.global.mbarrier::complete_tx::bytes "
                 "[%0], [%1], %2, [%3];"
                 :: "r"(dst), "l"(src), "r"(bytes), "r"(mbar) : "memory");
}
__device__ __forceinline__ void mbar_wait(uint32_t mbar, uint32_t parity) {
    asm volatile(
        "{\n\t.reg .pred P;\n\t"
        "WAITL_%=:\n\t"
        "mbarrier.try_wait.parity.acquire.cta.shared::cta.b64 P, [%0], %1, 0x989680;\n\t"
        "@P bra.uni WDONE_%=;\n\t"
        "bra.uni WAITL_%=;\n\t"
        "WDONE_%=:\n\t}"
        :: "r"(mbar), "r"(parity) : "memory");
}
__device__ __forceinline__ void red_u64(unsigned long long* p, unsigned long long v) {
    asm volatile("red.global.add.u64 [%0], %1;" :: "l"(p), "l"(v) : "memory");
}
__device__ __forceinline__ unsigned long long pack1(float sq) {
    return (1ULL << G_CNT_SHIFT) + (unsigned long long)(sq * P_SCALE + 0.5f);
}

// ---------------- block-local flush ----------------
// 64 threads, 128 clusters: thread t fully reduces columns t and t+64
// (64 entries = 16 uint4 each) and REDs straight to the global bin.
__device__ void flush_bins(unsigned* bins, int b_prim, int tid, bool rezero) {
    __syncthreads();
#pragma unroll
    for (int cc = 0; cc < 2; cc++) {
        const int c = tid + cc * THREADS;
        unsigned cnt = 0, sum = 0;
        const uint4* row = (const uint4*)&bins[c * THREADS];
#pragma unroll
        for (int j = 0; j < 16; j++) {
            uint4 v = row[(j + tid) & 15];  // stagger banks
            cnt += (v.x >> P_CNT_SHIFT) + (v.y >> P_CNT_SHIFT) +
                   (v.z >> P_CNT_SHIFT) + (v.w >> P_CNT_SHIFT);
            sum += (v.x & P_SUM_MASK) + (v.y & P_SUM_MASK) +
                   (v.z & P_SUM_MASK) + (v.w & P_SUM_MASK);
        }
        if (cnt)
            red_u64(&g_bins[b_prim * NUM_C + c].v,
                    ((unsigned long long)cnt << G_CNT_SHIFT) | (unsigned long long)sum);
        if (rezero) {
            uint4* zrow = (uint4*)&bins[c * THREADS];
#pragma unroll
            for (int j = 0; j < 16; j++) zrow[j] = make_uint4(0u, 0u, 0u, 0u);
        }
    }
    __syncthreads();
}

// ---------------- main kernel ----------------
__global__ void __launch_bounds__(THREADS)
fused_loss_kernel(const float* __restrict__ reco,
                  const float* __restrict__ target,
                  const int* __restrict__ clabel,
                  const int* __restrict__ bindex,
                  int n, int n4, int chunk4, int nblocks,
                  float* __restrict__ out) {
    extern __shared__ __align__(128) char sm[];
    unsigned* bins = (unsigned*)sm;
    const uint32_t smb = smem_u32(sm);
    const int tid = threadIdx.x;
    const int start4 = blockIdx.x * chunk4;
    const int end4 = min(start4 + chunk4, n4);

    if (start4 < n4) {
        // zero own columns (t and t+64): 32 uint4 per thread
        {
            uint4* z = (uint4*)sm;
#pragma unroll
            for (int j = 0; j < 16; j++) {
                z[tid * 16 + j] = make_uint4(0u, 0u, 0u, 0u);
                z[(tid + THREADS) * 16 + j] = make_uint4(0u, 0u, 0u, 0u);
            }
        }
        if (tid == 0) {
#pragma unroll
            for (int b = 0; b < NBUF; b++) mbar_init(smb + OFF_MBAR + b * 8, 1);
        }
        __syncthreads();

        int b_prim = __ldg(&bindex[start4 * 4]);
        const int nst = (end4 - start4 + STAGE4 - 1) / STAGE4;

        // preload up to 3 stages (depth-4 ring: 1 computing + 3 in flight)
        if (tid == 0) {
            for (int p = 0; p < nst && p < NBUF - 1; p++) {
                int ss4 = start4 + p * STAGE4;
                uint32_t ab = (uint32_t)min(STAGE4, end4 - ss4) * 16;
                uint32_t mb = smb + OFF_MBAR + (p & (NBUF - 1)) * 8;
                uint32_t dst = smb + OFF_STAGE + (p & (NBUF - 1)) * BUF_STRIDE;
                mbar_expect_tx(mb, ab * 4);
                bulk_g2s(dst, (const char*)reco + (size_t)ss4 * 16, ab, mb);
                bulk_g2s(dst + ARR_BYTES, (const char*)target + (size_t)ss4 * 16, ab, mb);
                bulk_g2s(dst + 2 * ARR_BYTES, (const char*)clabel + (size_t)ss4 * 16, ab, mb);
                bulk_g2s(dst + 3 * ARR_BYTES, (const char*)bindex + (size_t)ss4 * 16, ab, mb);
            }
        }

        for (int s = 0; s < nst; s++) {
            const int buf = s & (NBUF - 1);

            // refill the ring: stage s+3 goes into buf (s-1)&3, freed at end of s-1
            if (tid == 0 && s + NBUF - 1 < nst) {
                int p = s + NBUF - 1;
                int ss4 = start4 + p * STAGE4;
                uint32_t ab = (uint32_t)min(STAGE4, end4 - ss4) * 16;
                uint32_t mb = smb + OFF_MBAR + (p & (NBUF - 1)) * 8;
                uint32_t dst = smb + OFF_STAGE + (p & (NBUF - 1)) * BUF_STRIDE;
                mbar_expect_tx(mb, ab * 4);
                bulk_g2s(dst, (const char*)reco + (size_t)ss4 * 16, ab, mb);
                bulk_g2s(dst + ARR_BYTES, (const char*)target + (size_t)ss4 * 16, ab, mb);
                bulk_g2s(dst + 2 * ARR_BYTES, (const char*)clabel + (size_t)ss4 * 16, ab, mb);
                bulk_g2s(dst + 3 * ARR_BYTES, (const char*)bindex + (size_t)ss4 * 16, ab, mb);
            }

            mbar_wait(smb + OFF_MBAR + buf * 8, (s >> 2) & 1);

            const int len4 = min(STAGE4, end4 - (start4 + s * STAGE4));
            const char* base = sm + OFF_STAGE + buf * BUF_STRIDE;
            const float4* sr = (const float4*)base;
            const float4* st = (const float4*)(base + ARR_BYTES);
            const int4* sc = (const int4*)(base + 2 * ARR_BYTES);
            const int* sbi = (const int*)(base + 3 * ARR_BYTES);

            const int b_first = sbi[0];
            const int b_last = sbi[len4 * 4 - 1];
            if (b_first != b_prim) {            // batch boundary crossed
                flush_bins(bins, b_prim, tid, true);
                b_prim = b_first;
            }

            if (b_last == b_prim) {
                // fast path: whole stage is one batch (no asm clobbers here)
#pragma unroll
                for (int k = 0; k < 2; k++) {
                    int j = tid + k * THREADS;
                    if (j < len4) {
                        float4 r = sr[j];
                        float4 t = st[j];
                        int4 c = sc[j];
                        float d0 = r.x - t.x, d1 = r.y - t.y;
                        float d2 = r.z - t.z, d3 = r.w - t.w;
                        bins[c.x * THREADS + tid] +=
                            (1u << P_CNT_SHIFT) + (unsigned)(d0 * d0 * P_SCALE + 0.5f);
                        bins[c.y * THREADS + tid] +=
                            (1u << P_CNT_SHIFT) + (unsigned)(d1 * d1 * P_SCALE + 0.5f);
                        bins[c.z * THREADS + tid] +=
                            (1u << P_CNT_SHIFT) + (unsigned)(d2 * d2 * P_SCALE + 0.5f);
                        bins[c.w * THREADS + tid] +=
                            (1u << P_CNT_SHIFT) + (unsigned)(d3 * d3 * P_SCALE + 0.5f);
                    }
                }
            } else {
                // mixed stage (rare): per-element batch check
                const int4* sb4 = (const int4*)sbi;
#pragma unroll
                for (int k = 0; k < 2; k++) {
                    int j = tid + k * THREADS;
                    if (j < len4) {
                        float4 r = sr[j];
                        float4 t = st[j];
                        int4 c = sc[j];
                        int4 b = sb4[j];
                        float d0 = r.x - t.x, d1 = r.y - t.y;
                        float d2 = r.z - t.z, d3 = r.w - t.w;
                        float s0 = d0 * d0, s1 = d1 * d1, s2 = d2 * d2, s3 = d3 * d3;
                        if (b.x == b_prim)
                            bins[c.x * THREADS + tid] +=
                                (1u << P_CNT_SHIFT) + (unsigned)(s0 * P_SCALE + 0.5f);
                        else red_u64(&g_bins[b.x * NUM_C + c.x].v, pack1(s0));
                        if (b.y == b_prim)
                            bins[c.y * THREADS + tid] +=
                                (1u << P_CNT_SHIFT) + (unsigned)(s1 * P_SCALE + 0.5f);
                        else red_u64(&g_bins[b.y * NUM_C + c.y].v, pack1(s1));
                        if (b.z == b_prim)
                            bins[c.z * THREADS + tid] +=
                                (1u << P_CNT_SHIFT) + (unsigned)(s2 * P_SCALE + 0.5f);
                        else red_u64(&g_bins[b.z * NUM_C + c.z].v, pack1(s2));
                        if (b.w == b_prim)
                            bins[c.w * THREADS + tid] +=
                                (1u << P_CNT_SHIFT) + (unsigned)(s3 * P_SCALE + 0.5f);
                        else red_u64(&g_bins[b.w * NUM_C + c.w].v, pack1(s3));
                    }
                }
            }
            __syncthreads();  // all reads done before this buffer is refilled
        }

        // scalar tail (n % 4 != 0), last chunk only
        if (end4 == n4) {
            for (int i = n4 * 4 + tid; i < n; i += THREADS) {
                float d = __ldg(&reco[i]) - __ldg(&target[i]);
                red_u64(&g_bins[__ldg(&bindex[i]) * NUM_C + __ldg(&clabel[i])].v,
                        pack1(d * d));
            }
        }
        flush_bins(bins, b_prim, tid, false);
    }

    // ---- completion counter; last block finalizes ----
    __threadfence();
    __syncthreads();
    __shared__ unsigned int s_is_last;
    if (tid == 0) {
        unsigned int old = atomicAdd(&g_done, 1u);
        s_is_last = (old == (unsigned int)(nblocks - 1)) ? 1u : 0u;
    }
    __syncthreads();
    if (!s_is_last) return;
    __threadfence();

    __shared__ float s_bsum[NUM_B];
    __shared__ float s_bcnt[NUM_B];
    if (tid < NUM_B) {
        s_bsum[tid] = 0.0f;
        s_bcnt[tid] = 0.0f;
    }
    __syncthreads();

    for (int sg = tid; sg < NSEG; sg += THREADS) {
        unsigned long long v = __ldcg(&g_bins[sg].v);
        g_bins[sg].v = 0ULL;  // re-zero for next launch
        unsigned int cnt = (unsigned int)(v >> G_CNT_SHIFT);
        if (cnt) {
            float sum = (float)(v & G_SUM_MASK) * INV_SCALE;
            atomicAdd(&s_bsum[sg >> 7], sum / (float)cnt);
            atomicAdd(&s_bcnt[sg >> 7], 1.0f);
        }
    }
    __syncthreads();

    if (tid < 32) {
        float bl = 0.0f, bp = 0.0f;
        float c = s_bcnt[tid];
        if (c > 0.0f) {
            bl = s_bsum[tid] / c;
            bp = 1.0f;
        }
#pragma unroll
        for (int off = 16; off > 0; off >>= 1) {
            bl += __shfl_down_sync(0xFFFFFFFFu, bl, off);
            bp += __shfl_down_sync(0xFFFFFFFFu, bp, off);
        }
        if (tid == 0) {
            out[0] = bl / bp;
            g_done = 0u;  // reset for next launch
        }
    }
}

extern "C" void kernel_launch(void* const* d_in, const int* in_sizes, int n_in,
                              void* d_out, int out_size) {
    const float* reco = (const float*)d_in[0];
    const float* target = (const float*)d_in[1];
    const int* clabel = (const int*)d_in[2];
    const int* bindex = (const int*)d_in[3];
    float* out = (float*)d_out;

    const int n = in_sizes[0];
    const int n4 = n >> 2;
    const int chunk4 = (n4 + GRID_BLOCKS - 1) / GRID_BLOCKS;

    cudaFuncSetAttribute(fused_loss_kernel,
                         cudaFuncAttributeMaxDynamicSharedMemorySize, SMEM_BYTES);

    fused_loss_kernel<<<GRID_BLOCKS, THREADS, SMEM_BYTES>>>(
        reco, target, clabel, bindex, n, n4, chunk4, GRID_BLOCKS, out);
}

// round 11
// speedup vs baseline: 1.7224x; 1.7224x over previous
#include <cuda_runtime.h>
#include <cstdint>

#define NUM_B 32
#define NUM_C 128
#define NSEG (NUM_B * NUM_C)

#define THREADS 256
#define GRID_BLOCKS 152            // 1 CTA/SM, one wave

// Per-thread u32 bins: bits[0:24) = sum * 2^14, bits[24:32) = count.
#define P_CNT_SHIFT 24
#define P_SUM_MASK ((1u << P_CNT_SHIFT) - 1u)
#define P_SCALE 16384.0f
// Global u64 bins: bits[0:40) = sum * 2^14, bits[40:64) = count.
#define G_CNT_SHIFT 40
#define G_SUM_MASK ((1ULL << G_CNT_SHIFT) - 1ULL)
#define INV_SCALE (1.0f / 16384.0f)

// Stage: 256 float4 per array (1024 elements); 8-deep per-thread cp.async ring.
// Only reco/target/clabel are streamed (bindex handled by one binary search).
#define STAGE4 256
#define NBUF 8
#define ARR_BYTES (STAGE4 * 16)            // 4096
#define BUF_STRIDE (3 * ARR_BYTES)         // 12288
#define OFF_STAGE (THREADS * NUM_C * 4)    // 131072 (bins first)
#define SMEM_BYTES (OFF_STAGE + NBUF * BUF_STRIDE)  // 229376

struct alignas(128) PadBin {
    unsigned long long v;
    unsigned long long pad[15];
};
__device__ PadBin g_bins[NSEG];   // zero-init; last block re-zeros each run
__device__ unsigned int g_done;

// ---------------- PTX helpers ----------------
__device__ __forceinline__ uint32_t smem_u32(const void* p) {
    uint32_t a;
    asm("{ .reg .u64 t; cvta.to.shared.u64 t, %1; cvt.u32.u64 %0, t; }"
        : "=r"(a) : "l"(p));
    return a;
}
__device__ __forceinline__ void cp16(uint32_t dst, const void* src) {
    asm volatile("cp.async.cg.shared.global [%0], [%1], 16;"
                 :: "r"(dst), "l"(src) : "memory");
}
__device__ __forceinline__ void cp_commit() {
    asm volatile("cp.async.commit_group;" ::: "memory");
}
__device__ __forceinline__ void cp_wait_all_but7() {
    asm volatile("cp.async.wait_group 7;" ::: "memory");
}
__device__ __forceinline__ void red_u64(unsigned long long* p, unsigned long long v) {
    asm volatile("red.global.add.u64 [%0], %1;" :: "l"(p), "l"(v) : "memory");
}
__device__ __forceinline__ unsigned long long pack1(float sq) {
    return (1ULL << G_CNT_SHIFT) + (unsigned long long)(sq * P_SCALE + 0.5f);
}

// Issue stage p: each thread copies exactly the float4 it will later consume.
__device__ __forceinline__ void issue_stage(
    int p, int nst, int start4, int end4, int tid, uint32_t smb,
    const char* reco, const char* target, const char* clabel) {
    if (p < nst) {
        int ss4 = start4 + p * STAGE4;
        int len = min(STAGE4, end4 - ss4);
        if (tid < len) {
            uint32_t dst = smb + OFF_STAGE + (p & (NBUF - 1)) * BUF_STRIDE + tid * 16;
            size_t go = (size_t)(ss4 + tid) * 16;
            cp16(dst, reco + go);
            cp16(dst + ARR_BYTES, target + go);
            cp16(dst + 2 * ARR_BYTES, clabel + go);
        }
    }
    cp_commit();  // uniform: keeps group counting exact even for empty stages
}

// ---------------- block-local flush ----------------
__device__ void flush_bins(unsigned* bins, int b_prim, int tid, bool rezero) {
    __syncthreads();
    const int c = tid & (NUM_C - 1);
    const int h = tid >> 7;
    unsigned cnt = 0, sum = 0;
    const uint4* row = (const uint4*)&bins[c * THREADS + h * 128];
#pragma unroll 8
    for (int j = 0; j < 32; j++) {
        uint4 v = row[(j + tid) & 31];
        cnt += (v.x >> P_CNT_SHIFT) + (v.y >> P_CNT_SHIFT) +
               (v.z >> P_CNT_SHIFT) + (v.w >> P_CNT_SHIFT);
        sum += (v.x & P_SUM_MASK) + (v.y & P_SUM_MASK) +
               (v.z & P_SUM_MASK) + (v.w & P_SUM_MASK);
    }
    __syncthreads();
    bins[tid] = sum;
    bins[THREADS + tid] = cnt;
    __syncthreads();
    if (tid < NUM_C) {
        unsigned ts = sum + bins[tid + 128];
        unsigned tc = cnt + bins[THREADS + tid + 128];
        if (tc)
            red_u64(&g_bins[b_prim * NUM_C + tid].v,
                    ((unsigned long long)tc << G_CNT_SHIFT) | (unsigned long long)ts);
    }
    if (rezero) {
        __syncthreads();
        uint4* z = (uint4*)bins;
#pragma unroll
        for (int j = 0; j < 32; j++) z[tid * 32 + j] = make_uint4(0u, 0u, 0u, 0u);
    }
    __syncthreads();
}

// ---------------- main kernel ----------------
__global__ void __launch_bounds__(THREADS)
fused_loss_kernel(const float* __restrict__ reco,
                  const float* __restrict__ target,
                  const int* __restrict__ clabel,
                  const int* __restrict__ bindex,
                  int n, int n4, int chunk4, int nblocks,
                  float* __restrict__ out) {
    extern __shared__ __align__(128) char sm[];
    unsigned* bins = (unsigned*)sm;
    const uint32_t smb = smem_u32(sm);
    const int tid = threadIdx.x;
    const int start4 = blockIdx.x * chunk4;
    const int end4 = min(start4 + chunk4, n4);

    __shared__ int s_lo, s_hi;

    if (start4 < n4) {
        // zero private bins (128 KB)
        {
            uint4* z = (uint4*)sm;
#pragma unroll
            for (int j = 0; j < 32; j++) z[tid * 32 + j] = make_uint4(0u, 0u, 0u, 0u);
        }

        const bool last_chunk = (end4 == n4);
        const int E0 = start4 * 4;
        const int E1 = last_chunk ? (n - 1) : (end4 * 4 - 1);
        const int b0 = __ldg(&bindex[E0]);
        const int b1 = __ldg(&bindex[E1]);

        // Cooperative binary search for split S = first element with bindex>=b1.
        int S = 0x7fffffff;
        if (b0 != b1) {
            if (tid == 0) { s_lo = E0; s_hi = E1; }
            __syncthreads();
            while (true) {
                int lo = s_lo, hi = s_hi;
                if (hi - lo <= 1) break;
                __syncthreads();
                long span = hi - lo;
                int pos = lo + (int)((span * (long)(tid + 1)) / (THREADS + 1));
                if (pos > lo && pos < hi) {
                    if (__ldg(&bindex[pos]) < b1) atomicMax(&s_lo, pos);
                    else                          atomicMin(&s_hi, pos);
                }
                __syncthreads();
            }
            S = s_hi;
        }
        __syncthreads();  // bins zeroed + search done before stream phase

        const int nst = (end4 - start4 + STAGE4 - 1) / STAGE4;
        const int s_mix = (b0 != b1) ? ((S - E0) >> 10) : 0x7fffffff;  // 1024 el/stage
        int b_cur = b0;

        // preload NBUF-1 stages (per-thread groups)
        for (int p = 0; p < NBUF - 1; p++)
            issue_stage(p, nst, start4, end4, tid, smb,
                        (const char*)reco, (const char*)target, (const char*)clabel);

        // barrier-free stream loop: buffers and bins are thread-partitioned
        for (int s = 0; s < nst; s++) {
            issue_stage(s + NBUF - 1, nst, start4, end4, tid, smb,
                        (const char*)reco, (const char*)target, (const char*)clabel);
            cp_wait_all_but7();  // own stage-s copies resident

            int ss4 = start4 + s * STAGE4;
            int len = min(STAGE4, end4 - ss4);
            const char* base = sm + OFF_STAGE + (s & (NBUF - 1)) * BUF_STRIDE;

            if (tid < len) {
                float4 r = *(const float4*)(base + tid * 16);
                float4 t = *(const float4*)(base + ARR_BYTES + tid * 16);
                int4 c = *(const int4*)(base + 2 * ARR_BYTES + tid * 16);
                float d0 = r.x - t.x, d1 = r.y - t.y;
                float d2 = r.z - t.z, d3 = r.w - t.w;
                float q0 = d0 * d0, q1 = d1 * d1, q2 = d2 * d2, q3 = d3 * d3;

                if (s != s_mix) {
                    bins[c.x * THREADS + tid] +=
                        (1u << P_CNT_SHIFT) + (unsigned)(q0 * P_SCALE + 0.5f);
                    bins[c.y * THREADS + tid] +=
                        (1u << P_CNT_SHIFT) + (unsigned)(q1 * P_SCALE + 0.5f);
                    bins[c.z * THREADS + tid] +=
                        (1u << P_CNT_SHIFT) + (unsigned)(q2 * P_SCALE + 0.5f);
                    bins[c.w * THREADS + tid] +=
                        (1u << P_CNT_SHIFT) + (unsigned)(q3 * P_SCALE + 0.5f);
                } else {
                    int e = (ss4 + tid) * 4;
                    if (e + 0 < S)
                        bins[c.x * THREADS + tid] +=
                            (1u << P_CNT_SHIFT) + (unsigned)(q0 * P_SCALE + 0.5f);
                    else red_u64(&g_bins[b1 * NUM_C + c.x].v, pack1(q0));
                    if (e + 1 < S)
                        bins[c.y * THREADS + tid] +=
                            (1u << P_CNT_SHIFT) + (unsigned)(q1 * P_SCALE + 0.5f);
                    else red_u64(&g_bins[b1 * NUM_C + c.y].v, pack1(q1));
                    if (e + 2 < S)
                        bins[c.z * THREADS + tid] +=
                            (1u << P_CNT_SHIFT) + (unsigned)(q2 * P_SCALE + 0.5f);
                    else red_u64(&g_bins[b1 * NUM_C + c.z].v, pack1(q2));
                    if (e + 3 < S)
                        bins[c.w * THREADS + tid] +=
                            (1u << P_CNT_SHIFT) + (unsigned)(q3 * P_SCALE + 0.5f);
                    else red_u64(&g_bins[b1 * NUM_C + c.w].v, pack1(q3));
                }
            }

            if (s == s_mix) {                 // block-collective (uniform s)
                flush_bins(bins, b0, tid, true);
                b_cur = b1;
            }
        }

        // scalar tail (n % 4 != 0), last chunk only
        if (last_chunk) {
            for (int i = n4 * 4 + tid; i < n; i += THREADS) {
                float d = __ldg(&reco[i]) - __ldg(&target[i]);
                red_u64(&g_bins[__ldg(&bindex[i]) * NUM_C + __ldg(&clabel[i])].v,
                        pack1(d * d));
            }
        }
        flush_bins(bins, b_cur, tid, false);
    }

    // ---- completion counter; last block finalizes ----
    __threadfence();
    __syncthreads();
    __shared__ unsigned int s_is_last;
    if (tid == 0) {
        unsigned int old = atomicAdd(&g_done, 1u);
        s_is_last = (old == (unsigned int)(nblocks - 1)) ? 1u : 0u;
    }
    __syncthreads();
    if (!s_is_last) return;
    __threadfence();

    __shared__ float s_bsum[NUM_B];
    __shared__ float s_bcnt[NUM_B];
    if (tid < NUM_B) {
        s_bsum[tid] = 0.0f;
        s_bcnt[tid] = 0.0f;
    }
    __syncthreads();

    for (int sg = tid; sg < NSEG; sg += THREADS) {
        unsigned long long v = __ldcg(&g_bins[sg].v);
        g_bins[sg].v = 0ULL;  // re-zero for next launch
        unsigned int cnt = (unsigned int)(v >> G_CNT_SHIFT);
        if (cnt) {
            float sum = (float)(v & G_SUM_MASK) * INV_SCALE;
            atomicAdd(&s_bsum[sg >> 7], sum / (float)cnt);
            atomicAdd(&s_bcnt[sg >> 7], 1.0f);
        }
    }
    __syncthreads();

    if (tid < 32) {
        float bl = 0.0f, bp = 0.0f;
        float c = s_bcnt[tid];
        if (c > 0.0f) {
            bl = s_bsum[tid] / c;
            bp = 1.0f;
        }
#pragma unroll
        for (int off = 16; off > 0; off >>= 1) {
            bl += __shfl_down_sync(0xFFFFFFFFu, bl, off);
            bp += __shfl_down_sync(0xFFFFFFFFu, bp, off);
        }
        if (tid == 0) {
            out[0] = bl / bp;
            g_done = 0u;  // reset for next launch
        }
    }
}

extern "C" void kernel_launch(void* const* d_in, const int* in_sizes, int n_in,
                              void* d_out, int out_size) {
    const float* reco = (const float*)d_in[0];
    const float* target = (const float*)d_in[1];
    const int* clabel = (const int*)d_in[2];
    const int* bindex = (const int*)d_in[3];
    float* out = (float*)d_out;

    const int n = in_sizes[0];
    const int n4 = n >> 2;
    const int chunk4 = (n4 + GRID_BLOCKS - 1) / GRID_BLOCKS;

    cudaFuncSetAttribute(fused_loss_kernel,
                         cudaFuncAttributeMaxDynamicSharedMemorySize, SMEM_BYTES);

    fused_loss_kernel<<<GRID_BLOCKS, THREADS, SMEM_BYTES>>>(
        reco, target, clabel, bindex, n, n4, chunk4, GRID_BLOCKS, out);
}

// round 14
// speedup vs baseline: 2.6352x; 1.5300x over previous
#include <cuda_runtime.h>
#include <cstdint>

#define NUM_B 32
#define NUM_C 128
#define NSEG (NUM_B * NUM_C)

#define THREADS 256
#define GRID_BLOCKS 152            // 1 CTA/SM, one wave

// Per-thread u32 bins: bits[0:24) = sum * 2^14, bits[24:32) = count.
#define P_CNT_SHIFT 24
#define P_SUM_MASK ((1u << P_CNT_SHIFT) - 1u)
#define P_SCALE 16384.0f
// Global u64 bins: bits[0:40) = sum * 2^14, bits[40:64) = count.
#define G_CNT_SHIFT 40
#define G_SUM_MASK ((1ULL << G_CNT_SHIFT) - 1ULL)
#define INV_SCALE (1.0f / 16384.0f)

// Stage: 256 float4 (1024 el) per array; reco/target/clabel only.
// Depth-8 TMA ring -> up to 7 groups (84 KB) in flight per SM.
#define STAGE4 256
#define NBUF 8
#define ARR_BYTES (STAGE4 * 16)            // 4096
#define BUF_STRIDE (3 * ARR_BYTES)         // 12288
#define OFF_STAGE (THREADS * NUM_C * 4)    // 131072 (bins first)
#define OFF_MBAR (OFF_STAGE + NBUF * BUF_STRIDE)   // 229376
#define SMEM_BYTES (OFF_MBAR + 128)        // 229504 (<= 232448 opt-in)

struct alignas(128) PadBin {
    unsigned long long v;
    unsigned long long pad[15];
};
__device__ PadBin g_bins[NSEG];   // zero-init; last block re-zeros each run
__device__ unsigned int g_done;

// ---------------- PTX helpers ----------------
__device__ __forceinline__ uint32_t smem_u32(const void* p) {
    uint32_t a;
    asm("{ .reg .u64 t; cvta.to.shared.u64 t, %1; cvt.u32.u64 %0, t; }"
        : "=r"(a) : "l"(p));
    return a;
}
__device__ __forceinline__ void mbar_init(uint32_t a, uint32_t cnt) {
    asm volatile("mbarrier.init.shared.b64 [%0], %1;" :: "r"(a), "r"(cnt) : "memory");
}
__device__ __forceinline__ void mbar_expect_tx(uint32_t a, uint32_t tx) {
    asm volatile("mbarrier.arrive.expect_tx.shared.b64 _, [%0], %1;"
                 :: "r"(a), "r"(tx) : "memory");
}
__device__ __forceinline__ void bulk_g2s(uint32_t dst, const void* src,
                                         uint32_t bytes, uint32_t mbar) {
    asm volatile("cp.async.bulk.shared::cta.global.mbarrier::complete_tx::bytes "
                 "[%0], [%1], %2, [%3];"
                 :: "r"(dst), "l"(src), "r"(bytes), "r"(mbar) : "memory");
}
__device__ __forceinline__ void mbar_wait(uint32_t mbar, uint32_t parity) {
    asm volatile(
        "{\n\t.reg .pred P;\n\t"
        "WAITL_%=:\n\t"
        "mbarrier.try_wait.parity.acquire.cta.shared::cta.b64 P, [%0], %1, 0x989680;\n\t"
        "@P bra.uni WDONE_%=;\n\t"
        "bra.uni WAITL_%=;\n\t"
        "WDONE_%=:\n\t}"
        :: "r"(mbar), "r"(parity) : "memory");
}
__device__ __forceinline__ void red_u64(unsigned long long* p, unsigned long long v) {
    asm volatile("red.global.add.u64 [%0], %1;" :: "l"(p), "l"(v) : "memory");
}
__device__ __forceinline__ unsigned long long pack1(float sq) {
    return (1ULL << G_CNT_SHIFT) + (unsigned long long)(sq * P_SCALE + 0.5f);
}

// Issue TMA group for stage p (tid 0 only).
__device__ __forceinline__ void issue_stage(
    int p, int nst, int start4, int end4, uint32_t smb,
    const char* reco, const char* target, const char* clabel) {
    if (p >= nst) return;
    int ss4 = start4 + p * STAGE4;
    uint32_t ab = (uint32_t)min(STAGE4, end4 - ss4) * 16;
    uint32_t mb = smb + OFF_MBAR + (p & (NBUF - 1)) * 8;
    uint32_t dst = smb + OFF_STAGE + (p & (NBUF - 1)) * BUF_STRIDE;
    size_t go = (size_t)ss4 * 16;
    mbar_expect_tx(mb, ab * 3);
    bulk_g2s(dst, reco + go, ab, mb);
    bulk_g2s(dst + ARR_BYTES, target + go, ab, mb);
    bulk_g2s(dst + 2 * ARR_BYTES, clabel + go, ab, mb);
}

// ---------------- block-local flush ----------------
__device__ void flush_bins(unsigned* bins, int b_prim, int tid, bool rezero) {
    __syncthreads();
    const int c = tid & (NUM_C - 1);
    const int h = tid >> 7;
    unsigned cnt = 0, sum = 0;
    const uint4* row = (const uint4*)&bins[c * THREADS + h * 128];
#pragma unroll 8
    for (int j = 0; j < 32; j++) {
        uint4 v = row[(j + tid) & 31];
        cnt += (v.x >> P_CNT_SHIFT) + (v.y >> P_CNT_SHIFT) +
               (v.z >> P_CNT_SHIFT) + (v.w >> P_CNT_SHIFT);
        sum += (v.x & P_SUM_MASK) + (v.y & P_SUM_MASK) +
               (v.z & P_SUM_MASK) + (v.w & P_SUM_MASK);
    }
    __syncthreads();
    bins[tid] = sum;
    bins[THREADS + tid] = cnt;
    __syncthreads();
    if (tid < NUM_C) {
        unsigned ts = sum + bins[tid + 128];
        unsigned tc = cnt + bins[THREADS + tid + 128];
        if (tc)
            red_u64(&g_bins[b_prim * NUM_C + tid].v,
                    ((unsigned long long)tc << G_CNT_SHIFT) | (unsigned long long)ts);
    }
    if (rezero) {
        __syncthreads();
        uint4* z = (uint4*)bins;
#pragma unroll
        for (int j = 0; j < 32; j++) z[tid * 32 + j] = make_uint4(0u, 0u, 0u, 0u);
    }
    __syncthreads();
}

// ---------------- main kernel ----------------
__global__ void __launch_bounds__(THREADS)
fused_loss_kernel(const float* __restrict__ reco,
                  const float* __restrict__ target,
                  const int* __restrict__ clabel,
                  const int* __restrict__ bindex,
                  int n, int n4, int chunk4, int nblocks,
                  float* __restrict__ out) {
    extern __shared__ __align__(128) char sm[];
    unsigned* bins = (unsigned*)sm;
    const uint32_t smb = smem_u32(sm);
    const int tid = threadIdx.x;
    const int start4 = blockIdx.x * chunk4;
    const int end4 = min(start4 + chunk4, n4);

    __shared__ int s_lo, s_hi;

    if (start4 < n4) {
        // zero private bins (128 KB) + init mbarriers
        {
            uint4* z = (uint4*)sm;
#pragma unroll
            for (int j = 0; j < 32; j++) z[tid * 32 + j] = make_uint4(0u, 0u, 0u, 0u);
        }
        if (tid == 0) {
#pragma unroll
            for (int b = 0; b < NBUF; b++) mbar_init(smb + OFF_MBAR + b * 8, 1);
        }

        const bool last_chunk = (end4 == n4);
        const int E0 = start4 * 4;
        const int E1 = last_chunk ? (n - 1) : (end4 * 4 - 1);
        const int b0 = __ldg(&bindex[E0]);
        const int b1 = __ldg(&bindex[E1]);
        __syncthreads();  // mbar init + bin zero visible

        // Kick the TMA ring ASAP (overlaps with the binary search below).
        if (tid == 0) {
            const int nst0 = (end4 - start4 + STAGE4 - 1) / STAGE4;
            for (int p = 0; p < NBUF - 1; p++)
                issue_stage(p, nst0, start4, end4, smb,
                            (const char*)reco, (const char*)target, (const char*)clabel);
        }

        // Cooperative binary search: S = first element with bindex >= b1.
        int S = 0x7fffffff;
        if (b0 != b1) {
            if (tid == 0) { s_lo = E0; s_hi = E1; }
            __syncthreads();
            while (true) {
                int lo = s_lo, hi = s_hi;
                if (hi - lo <= 1) break;
                __syncthreads();
                long span = hi - lo;
                int pos = lo + (int)((span * (long)(tid + 1)) / (THREADS + 1));
                if (pos > lo && pos < hi) {
                    if (__ldg(&bindex[pos]) < b1) atomicMax(&s_lo, pos);
                    else                          atomicMin(&s_hi, pos);
                }
                __syncthreads();
            }
            S = s_hi;
        }
        __syncthreads();

        const int nst = (end4 - start4 + STAGE4 - 1) / STAGE4;
        const int s_mix = (b0 != b1) ? ((S - E0) >> 10) : 0x7fffffff;
        int b_cur = b0;

        for (int s = 0; s < nst; s++) {
            const int buf = s & (NBUF - 1);
            // Refill: stage s+NBUF-1 -> buf (s-1)&7, consumed at iter s-1
            // (guarded by the end-of-iteration __syncthreads).
            if (tid == 0)
                issue_stage(s + NBUF - 1, nst, start4, end4, smb,
                            (const char*)reco, (const char*)target, (const char*)clabel);

            mbar_wait(smb + OFF_MBAR + buf * 8, (s >> 3) & 1);

            const int ss4 = start4 + s * STAGE4;
            const int len = min(STAGE4, end4 - ss4);
            const char* base = sm + OFF_STAGE + buf * BUF_STRIDE;

            if (tid < len) {
                float4 r = *(const float4*)(base + tid * 16);
                float4 t = *(const float4*)(base + ARR_BYTES + tid * 16);
                int4 c = *(const int4*)(base + 2 * ARR_BYTES + tid * 16);
                float d0 = r.x - t.x, d1 = r.y - t.y;
                float d2 = r.z - t.z, d3 = r.w - t.w;
                float q0 = d0 * d0, q1 = d1 * d1, q2 = d2 * d2, q3 = d3 * d3;

                if (s != s_mix) {
                    bins[c.x * THREADS + tid] +=
                        (1u << P_CNT_SHIFT) + (unsigned)(q0 * P_SCALE + 0.5f);
                    bins[c.y * THREADS + tid] +=
                        (1u << P_CNT_SHIFT) + (unsigned)(q1 * P_SCALE + 0.5f);
                    bins[c.z * THREADS + tid] +=
                        (1u << P_CNT_SHIFT) + (unsigned)(q2 * P_SCALE + 0.5f);
                    bins[c.w * THREADS + tid] +=
                        (1u << P_CNT_SHIFT) + (unsigned)(q3 * P_SCALE + 0.5f);
                } else {
                    int e = (ss4 + tid) * 4;
                    if (e + 0 < S)
                        bins[c.x * THREADS + tid] +=
                            (1u << P_CNT_SHIFT) + (unsigned)(q0 * P_SCALE + 0.5f);
                    else red_u64(&g_bins[b1 * NUM_C + c.x].v, pack1(q0));
                    if (e + 1 < S)
                        bins[c.y * THREADS + tid] +=
                            (1u << P_CNT_SHIFT) + (unsigned)(q1 * P_SCALE + 0.5f);
                    else red_u64(&g_bins[b1 * NUM_C + c.y].v, pack1(q1));
                    if (e + 2 < S)
                        bins[c.z * THREADS + tid] +=
                            (1u << P_CNT_SHIFT) + (unsigned)(q2 * P_SCALE + 0.5f);
                    else red_u64(&g_bins[b1 * NUM_C + c.z].v, pack1(q2));
                    if (e + 3 < S)
                        bins[c.w * THREADS + tid] +=
                            (1u << P_CNT_SHIFT) + (unsigned)(q3 * P_SCALE + 0.5f);
                    else red_u64(&g_bins[b1 * NUM_C + c.w].v, pack1(q3));
                }
            }

            if (s == s_mix) {                 // block-collective (uniform s)
                flush_bins(bins, b0, tid, true);
                b_cur = b1;
            }
            __syncthreads();  // all reads done before this buffer is refilled
        }

        // scalar tail (n % 4 != 0), last chunk only
        if (last_chunk) {
            for (int i = n4 * 4 + tid; i < n; i += THREADS) {
                float d = __ldg(&reco[i]) - __ldg(&target[i]);
                red_u64(&g_bins[__ldg(&bindex[i]) * NUM_C + __ldg(&clabel[i])].v,
                        pack1(d * d));
            }
        }
        flush_bins(bins, b_cur, tid, false);
    }

    // ---- completion counter; last block finalizes ----
    __threadfence();
    __syncthreads();
    __shared__ unsigned int s_is_last;
    if (tid == 0) {
        unsigned int old = atomicAdd(&g_done, 1u);
        s_is_last = (old == (unsigned int)(nblocks - 1)) ? 1u : 0u;
    }
    __syncthreads();
    if (!s_is_last) return;
    __threadfence();

    __shared__ float s_bsum[NUM_B];
    __shared__ float s_bcnt[NUM_B];
    if (tid < NUM_B) {
        s_bsum[tid] = 0.0f;
        s_bcnt[tid] = 0.0f;
    }
    __syncthreads();

    for (int sg = tid; sg < NSEG; sg += THREADS) {
        unsigned long long v = __ldcg(&g_bins[sg].v);
        g_bins[sg].v = 0ULL;  // re-zero for next launch
        unsigned int cnt = (unsigned int)(v >> G_CNT_SHIFT);
        if (cnt) {
            float sum = (float)(v & G_SUM_MASK) * INV_SCALE;
            atomicAdd(&s_bsum[sg >> 7], sum / (float)cnt);
            atomicAdd(&s_bcnt[sg >> 7], 1.0f);
        }
    }
    __syncthreads();

    if (tid < 32) {
        float bl = 0.0f, bp = 0.0f;
        float c = s_bcnt[tid];
        if (c > 0.0f) {
            bl = s_bsum[tid] / c;
            bp = 1.0f;
        }
#pragma unroll
        for (int off = 16; off > 0; off >>= 1) {
            bl += __shfl_down_sync(0xFFFFFFFFu, bl, off);
            bp += __shfl_down_sync(0xFFFFFFFFu, bp, off);
        }
        if (tid == 0) {
            out[0] = bl / bp;
            g_done = 0u;  // reset for next launch
        }
    }
}

extern "C" void kernel_launch(void* const* d_in, const int* in_sizes, int n_in,
                              void* d_out, int out_size) {
    const float* reco = (const float*)d_in[0];
    const float* target = (const float*)d_in[1];
    const int* clabel = (const int*)d_in[2];
    const int* bindex = (const int*)d_in[3];
    float* out = (float*)d_out;

    const int n = in_sizes[0];
    const int n4 = n >> 2;
    const int chunk4 = (n4 + GRID_BLOCKS - 1) / GRID_BLOCKS;

    cudaFuncSetAttribute(fused_loss_kernel,
                         cudaFuncAttributeMaxDynamicSharedMemorySize, SMEM_BYTES);

    fused_loss_kernel<<<GRID_BLOCKS, THREADS, SMEM_BYTES>>>(
        reco, target, clabel, bindex, n, n4, chunk4, GRID_BLOCKS, out);
}